// round 15
// baseline (speedup 1.0000x reference)
#include <cuda_runtime.h>
#include <cuda_bf16.h>

#define N_NODES   100000
#define N_EDGES   3200000
#define E_TOT     (N_EDGES + N_NODES)   // self loops appended
#define IN_DIM    512
#define HEADS     4
#define C1        8
#define C2        4
#define HC1       (HEADS*C1)   // 32
#define HC2       (HEADS*C2)   // 16
#define N_GRAPHS  64
#define OUT_DIM   10

#define SCAN_BS   1024
#define N_SCAN_BLOCKS ((N_NODES + SCAN_BS - 1) / SCAN_BS)   // 98

// ---------------- device scratch ----------------
__device__ __align__(16) unsigned g_h1b[(size_t)N_NODES * (HC1 / 2)];
__device__ __align__(16) float g_es1[(size_t)N_NODES * HEADS];
__device__ __align__(16) float g_ed1[(size_t)N_NODES * HEADS];

__device__ __align__(16) unsigned g_h2b[(size_t)N_NODES * (HC2 / 2)];
__device__ __align__(16) float g_es2[(size_t)N_NODES * HEADS];
__device__ __align__(16) float g_ed2[(size_t)N_NODES * HEADS];

__device__ __align__(16) float g_pool[N_GRAPHS * HC2];
__device__ float g_cnt [N_GRAPHS];

__device__ int g_deg[N_NODES];
__device__ int g_off[N_NODES + 1];
__device__ int g_pos[N_NODES];
__device__ int g_csr[E_TOT];
__device__ int g_blocksum[N_SCAN_BLOCKS];
__device__ int g_blockoff[N_SCAN_BLOCKS];

__device__ int g_is64;

// ---------------- helpers ----------------
__device__ __forceinline__ float lrelu(float v) { return v >= 0.f ? v : 0.2f * v; }

__device__ __forceinline__ void red4(float* p, float a, float b, float c, float d) {
    asm volatile("red.global.add.v4.f32 [%0], {%1,%2,%3,%4};"
                 :: "l"(p), "f"(a), "f"(b), "f"(c), "f"(d) : "memory");
}

__device__ __forceinline__ unsigned pack_bf2(float a, float b) {
    __nv_bfloat162 t = __floats2bfloat162_rn(a, b);
    return *(unsigned*)&t;
}
__device__ __forceinline__ float2 upk_bf2(unsigned u) {
    return __bfloat1622float2(*(__nv_bfloat162*)&u);
}

// ---------------- init (fused dtype detect) ----------------
__global__ void init_kernel(const void* ei) {
    int t = blockIdx.x * blockDim.x + threadIdx.x;
    if (t < N_NODES) g_deg[t] = 0;
    if (t < N_GRAPHS * HC2) g_pool[t] = 0.f;
    if (t < N_GRAPHS)       g_cnt[t]  = 0.f;
    if (blockIdx.x == 0) {
        const unsigned long long* p = (const unsigned long long*)ei;
        int big = (p[threadIdx.x] >= (unsigned long long)N_NODES) ? 1 : 0;
        unsigned any_big = __ballot_sync(0xffffffffu, big);
        __shared__ unsigned sb[8];
        if ((threadIdx.x & 31) == 0) sb[threadIdx.x >> 5] = any_big;
        __syncthreads();
        if (threadIdx.x == 0) {
            unsigned m = 0;
            #pragma unroll
            for (int i = 0; i < 8; i++) m |= sb[i];
            g_is64 = (m == 0) ? 1 : 0;
        }
    }
}

// ---------------- CSR build (vectorized 2 edges/thread) ----------------
// self-loop counts are folded into scan1 as +1 per node.
__global__ void count_kernel(const void* __restrict__ ei) {
    int i = blockIdx.x * blockDim.x + threadIdx.x;
    if (i >= N_EDGES / 2) return;
    int d0, d1;
    if (g_is64) {
        longlong2 v = ((const longlong2*)((const long long*)ei + N_EDGES))[i];
        d0 = (int)v.x; d1 = (int)v.y;
    } else {
        int2 v = ((const int2*)((const int*)ei + N_EDGES))[i];
        d0 = v.x; d1 = v.y;
    }
    atomicAdd(&g_deg[d0], 1);
    atomicAdd(&g_deg[d1], 1);
}

__global__ void scan1_kernel() {
    __shared__ int sm[SCAN_BS];
    const int t = threadIdx.x;
    const int idx = blockIdx.x * SCAN_BS + t;
    int v = (idx < N_NODES) ? (g_deg[idx] + 1) : 0;   // +1 = implicit self-loop count
    sm[t] = v;
    __syncthreads();
    #pragma unroll
    for (int off = 1; off < SCAN_BS; off <<= 1) {
        int u = (t >= off) ? sm[t - off] : 0;
        __syncthreads();
        sm[t] += u;
        __syncthreads();
    }
    if (idx < N_NODES) g_off[idx] = sm[t] - v;
    if (t == SCAN_BS - 1) g_blocksum[blockIdx.x] = sm[t];
}

__global__ void scan2_kernel() {
    __shared__ int sm[128];
    const int t = threadIdx.x;
    int v = (t < N_SCAN_BLOCKS) ? g_blocksum[t] : 0;
    sm[t] = v;
    __syncthreads();
    #pragma unroll
    for (int off = 1; off < 128; off <<= 1) {
        int u = (t >= off) ? sm[t - off] : 0;
        __syncthreads();
        sm[t] += u;
        __syncthreads();
    }
    if (t < N_SCAN_BLOCKS) g_blockoff[t] = sm[t] - v;
}

__global__ void scan3_kernel() {
    const int idx = blockIdx.x * blockDim.x + threadIdx.x;
    if (idx < N_NODES) {
        int o = g_off[idx] + g_blockoff[blockIdx.x];
        g_off[idx] = o;
        g_pos[idx] = o;
    }
    if (idx == 0) g_off[N_NODES] = E_TOT;
}

__global__ void scatter_kernel(const void* __restrict__ ei) {
    const int half = N_EDGES / 2;
    int i = blockIdx.x * blockDim.x + threadIdx.x;
    if (i < half) {
        int s0, s1, d0, d1;
        if (g_is64) {
            longlong2 sv = ((const longlong2*)ei)[i];
            longlong2 dv = ((const longlong2*)((const long long*)ei + N_EDGES))[i];
            s0 = (int)sv.x; s1 = (int)sv.y;
            d0 = (int)dv.x; d1 = (int)dv.y;
        } else {
            int2 sv = ((const int2*)ei)[i];
            int2 dv = ((const int2*)((const int*)ei + N_EDGES))[i];
            s0 = sv.x; s1 = sv.y;
            d0 = dv.x; d1 = dv.y;
        }
        g_csr[atomicAdd(&g_pos[d0], 1)] = s0;
        g_csr[atomicAdd(&g_pos[d1], 1)] = s1;
    } else if (i < half + N_NODES) {
        const int d = i - half;   // self loop
        g_csr[atomicAdd(&g_pos[d], 1)] = d;
    }
}

// ---------------- gemm1: h1 = x @ W1 (512->32), 8x8 register tile ------------
#define G1_BN 256
#define G1_BK 32
__global__ __launch_bounds__(128) void gemm1_kernel(const float* __restrict__ x,
                                                    const float* __restrict__ W1,
                                                    const float* __restrict__ a_src,
                                                    const float* __restrict__ a_dst) {
    __shared__ float sX[G1_BN][36];
    __shared__ float sW[G1_BK][36];
    const int tid = threadIdx.x;
    const int nbase = blockIdx.x * G1_BN;
    const int ng = tid >> 2;
    const int cg = tid & 3;
    const int c0 = cg * 8;

    float4 acc[8][2];
    #pragma unroll
    for (int j = 0; j < 8; j++) { acc[j][0] = make_float4(0,0,0,0); acc[j][1] = make_float4(0,0,0,0); }

    for (int k0 = 0; k0 < IN_DIM; k0 += G1_BK) {
        __syncthreads();
        for (int i = tid; i < G1_BN * (G1_BK / 4); i += 128) {
            int n = i >> 3, kv = i & 7;
            float4 v = make_float4(0,0,0,0);
            if (nbase + n < N_NODES)
                v = *(const float4*)(x + (size_t)(nbase + n) * IN_DIM + k0 + kv * 4);
            *(float4*)&sX[n][kv * 4] = v;
        }
        for (int i = tid; i < G1_BK * 32; i += 128) {
            int k = i >> 5, c = i & 31;
            sW[k][c] = W1[(size_t)(k0 + k) * 32 + c];
        }
        __syncthreads();
        #pragma unroll
        for (int k4 = 0; k4 < G1_BK; k4 += 4) {
            float4 xt[8];
            #pragma unroll
            for (int j = 0; j < 8; j++) xt[j] = *(const float4*)&sX[ng + j * 32][k4];
            #pragma unroll
            for (int kk = 0; kk < 4; kk++) {
                float4 w0 = *(const float4*)&sW[k4 + kk][c0];
                float4 w1 = *(const float4*)&sW[k4 + kk][c0 + 4];
                #pragma unroll
                for (int j = 0; j < 8; j++) {
                    float xv = (kk == 0) ? xt[j].x : (kk == 1) ? xt[j].y : (kk == 2) ? xt[j].z : xt[j].w;
                    acc[j][0].x += xv * w0.x; acc[j][0].y += xv * w0.y;
                    acc[j][0].z += xv * w0.z; acc[j][0].w += xv * w0.w;
                    acc[j][1].x += xv * w1.x; acc[j][1].y += xv * w1.y;
                    acc[j][1].z += xv * w1.z; acc[j][1].w += xv * w1.w;
                }
            }
        }
    }

    float as0 = a_src[c0+0], as1 = a_src[c0+1], as2 = a_src[c0+2], as3 = a_src[c0+3];
    float as4 = a_src[c0+4], as5 = a_src[c0+5], as6 = a_src[c0+6], as7 = a_src[c0+7];
    float ad0 = a_dst[c0+0], ad1 = a_dst[c0+1], ad2 = a_dst[c0+2], ad3 = a_dst[c0+3];
    float ad4 = a_dst[c0+4], ad5 = a_dst[c0+5], ad6 = a_dst[c0+6], ad7 = a_dst[c0+7];
    #pragma unroll
    for (int j = 0; j < 8; j++) {
        int n = nbase + ng + j * 32;
        if (n >= N_NODES) continue;
        uint4 hb;
        hb.x = pack_bf2(acc[j][0].x, acc[j][0].y);
        hb.y = pack_bf2(acc[j][0].z, acc[j][0].w);
        hb.z = pack_bf2(acc[j][1].x, acc[j][1].y);
        hb.w = pack_bf2(acc[j][1].z, acc[j][1].w);
        *(uint4*)&g_h1b[(size_t)n * (HC1/2) + cg * 4] = hb;
        float es = acc[j][0].x*as0 + acc[j][0].y*as1 + acc[j][0].z*as2 + acc[j][0].w*as3
                 + acc[j][1].x*as4 + acc[j][1].y*as5 + acc[j][1].z*as6 + acc[j][1].w*as7;
        float ed = acc[j][0].x*ad0 + acc[j][0].y*ad1 + acc[j][0].z*ad2 + acc[j][0].w*ad3
                 + acc[j][1].x*ad4 + acc[j][1].y*ad5 + acc[j][1].z*ad6 + acc[j][1].w*ad7;
        g_es1[(size_t)n * HEADS + cg] = es;
        g_ed1[(size_t)n * HEADS + cg] = ed;
    }
}

// ---------------- agg1: full-lane aggregation (bf16 gathers) + fused gemm2 ---
__global__ __launch_bounds__(256) void agg1_kernel(const float* __restrict__ b1,
                                                   const float* __restrict__ W2,
                                                   const float* __restrict__ a_src2,
                                                   const float* __restrict__ a_dst2) {
    __shared__ float sW2[HC1 * HC2];
    __shared__ __align__(16) float sB1[HC1];
    __shared__ float sA2s[HC2], sA2d[HC2];
    {
        const int t = threadIdx.x;
        for (int i = t; i < HC1 * HC2; i += 256) sW2[i] = W2[i];
        if (t < HC1) sB1[t] = b1[t];
        if (t < HC2) { sA2s[t] = a_src2[t]; sA2d[t] = a_dst2[t]; }
        __syncthreads();
    }

    const int warp = (blockIdx.x * blockDim.x + threadIdx.x) >> 5;
    if (warp >= N_NODES) return;
    const int lane = threadIdx.x & 31;
    const int d    = warp;
    const int beg  = g_off[d];
    const int end  = g_off[d + 1];
    const int le = lane >> 2, lh = lane & 3;   // exp phase: edge slot, head
    const int e  = lane >> 3, p = lane & 7;    // gather phase: edge-in-half, part
    const int hp = p >> 1;                     // head of part p

    const float edv_s = g_ed1[(size_t)d * 4 + lh];

    float  den_l = 0.f;
    float4 acc = make_float4(0,0,0,0);

    for (int base = beg; base < end; base += 8) {
        const int idx = base + le;
        int s_e = -1; float w = 0.f;
        if (idx < end) {
            s_e = g_csr[idx];
            float es_s = g_es1[(size_t)s_e * 4 + lh];
            w = __expf(lrelu(es_s + edv_s));
            den_l += w;
        }
        #pragma unroll
        for (int j = 0; j < 2; j++) {
            const int he = e + j * 4;                            // edge slot 0..7
            const int s_h = __shfl_sync(0xffffffffu, s_e, he * 4);
            const float w_h = __shfl_sync(0xffffffffu, w, he * 4 + hp);
            if (s_h >= 0) {
                uint2 hv = *(const uint2*)(g_h1b + (size_t)s_h * (HC1/2) + p * 2);
                float2 f0 = upk_bf2(hv.x), f1 = upk_bf2(hv.y);
                acc.x += w_h * f0.x; acc.y += w_h * f0.y;
                acc.z += w_h * f1.x; acc.w += w_h * f1.y;
            }
        }
    }

    #pragma unroll
    for (int o = 8; o <= 16; o <<= 1) {
        acc.x += __shfl_xor_sync(0xffffffffu, acc.x, o);
        acc.y += __shfl_xor_sync(0xffffffffu, acc.y, o);
        acc.z += __shfl_xor_sync(0xffffffffu, acc.z, o);
        acc.w += __shfl_xor_sync(0xffffffffu, acc.w, o);
    }
    #pragma unroll
    for (int o = 4; o <= 16; o <<= 1)
        den_l += __shfl_xor_sync(0xffffffffu, den_l, o);
    const float den_h = __shfl_sync(0xffffffffu, den_l, hp);
    const float ih = 1.f / (den_h + 1e-16f);

    float4 bb = *(const float4*)&sB1[p * 4];
    float r0 = fmaxf(acc.x * ih + bb.x, 0.f);
    float r1 = fmaxf(acc.y * ih + bb.y, 0.f);
    float r2 = fmaxf(acc.z * ih + bb.z, 0.f);
    float r3 = fmaxf(acc.w * ih + bb.w, 0.f);

    const int k0 = p * 4, c0 = e * 4;
    float4 pc = make_float4(0,0,0,0);
    #pragma unroll
    for (int kk = 0; kk < 4; kk++) {
        float rv = kk == 0 ? r0 : kk == 1 ? r1 : kk == 2 ? r2 : r3;
        const float* wrow = &sW2[(k0 + kk) * HC2 + c0];
        pc.x += rv * wrow[0]; pc.y += rv * wrow[1];
        pc.z += rv * wrow[2]; pc.w += rv * wrow[3];
    }
    #pragma unroll
    for (int o = 1; o <= 4; o <<= 1) {
        pc.x += __shfl_xor_sync(0xffffffffu, pc.x, o);
        pc.y += __shfl_xor_sync(0xffffffffu, pc.y, o);
        pc.z += __shfl_xor_sync(0xffffffffu, pc.z, o);
        pc.w += __shfl_xor_sync(0xffffffffu, pc.w, o);
    }
    if (p == 0) {
        *(uint2*)&g_h2b[(size_t)d * (HC2/2) + e * 2] =
            make_uint2(pack_bf2(pc.x, pc.y), pack_bf2(pc.z, pc.w));
        float es = pc.x * sA2s[c0] + pc.y * sA2s[c0+1] + pc.z * sA2s[c0+2] + pc.w * sA2s[c0+3];
        float ed = pc.x * sA2d[c0] + pc.y * sA2d[c0+1] + pc.z * sA2d[c0+2] + pc.w * sA2d[c0+3];
        g_es2[(size_t)d * HEADS + e] = es;
        g_ed2[(size_t)d * HEADS + e] = ed;
    }
}

// ---------------- agg2: full-lane aggregation (bf16 gathers) + relu+pool -----
__global__ __launch_bounds__(256) void agg2_kernel(const float* __restrict__ b2,
                                                   const void* __restrict__ batch) {
    __shared__ __align__(16) float sB2[HC2];
    if (threadIdx.x < HC2) sB2[threadIdx.x] = b2[threadIdx.x];
    __syncthreads();

    const int warp = (blockIdx.x * blockDim.x + threadIdx.x) >> 5;
    if (warp >= N_NODES) return;
    const int lane = threadIdx.x & 31;
    const int d    = warp;
    const int beg  = g_off[d];
    const int end  = g_off[d + 1];
    const int le = lane >> 2, lh = lane & 3;

    const float edv_s = g_ed2[(size_t)d * 4 + lh];

    float  den_l = 0.f;
    float4 acc = make_float4(0,0,0,0);

    for (int base = beg; base < end; base += 8) {
        const int idx = base + le;
        if (idx < end) {
            int s = g_csr[idx];
            float es_s = g_es2[(size_t)s * 4 + lh];
            float w = __expf(lrelu(es_s + edv_s));
            den_l += w;
            uint2 hv = *(const uint2*)(g_h2b + (size_t)s * (HC2/2) + lh * 2);
            float2 f0 = upk_bf2(hv.x), f1 = upk_bf2(hv.y);
            acc.x += w * f0.x; acc.y += w * f0.y;
            acc.z += w * f1.x; acc.w += w * f1.y;
        }
    }

    #pragma unroll
    for (int o = 4; o <= 16; o <<= 1) {
        den_l += __shfl_xor_sync(0xffffffffu, den_l, o);
        acc.x += __shfl_xor_sync(0xffffffffu, acc.x, o);
        acc.y += __shfl_xor_sync(0xffffffffu, acc.y, o);
        acc.z += __shfl_xor_sync(0xffffffffu, acc.z, o);
        acc.w += __shfl_xor_sync(0xffffffffu, acc.w, o);
    }

    if (lane < 4) {
        int g;
        if (g_is64) g = (int)((const long long*)batch)[d];
        else        g = ((const int*)batch)[d];
        const float ih = 1.f / (den_l + 1e-16f);
        float4 bb = *(const float4*)&sB2[lane * 4];
        float o0 = fmaxf(acc.x * ih + bb.x, 0.f);
        float o1 = fmaxf(acc.y * ih + bb.y, 0.f);
        float o2 = fmaxf(acc.z * ih + bb.z, 0.f);
        float o3 = fmaxf(acc.w * ih + bb.w, 0.f);
        red4(g_pool + g * HC2 + lane * 4, o0, o1, o2, o3);
        if (lane == 0) atomicAdd(&g_cnt[g], 1.f);
    }
}

// ---------------- final ----------------
__global__ void final_kernel(const float* __restrict__ Wf, const float* __restrict__ bf,
                             float* __restrict__ out) {
    const int t = threadIdx.x;
    if (t >= N_GRAPHS * OUT_DIM) return;
    const int g = t / OUT_DIM;
    const int o = t % OUT_DIM;
    const float c = fmaxf(g_cnt[g], 1.f);
    float acc = bf[o];
    #pragma unroll
    for (int j = 0; j < HC2; j++)
        acc += (g_pool[g * HC2 + j] / c) * Wf[j * OUT_DIM + o];
    out[t] = acc;
}

// ---------------- stream/event holder ----------------
struct StreamHolder {
    cudaStream_t s2 = nullptr;
    cudaEvent_t  ev0 = nullptr, ev1 = nullptr;
    bool ok = false;
    StreamHolder() {
        if (cudaStreamCreateWithFlags(&s2, cudaStreamNonBlocking) != cudaSuccess) return;
        if (cudaEventCreateWithFlags(&ev0, cudaEventDisableTiming) != cudaSuccess) return;
        if (cudaEventCreateWithFlags(&ev1, cudaEventDisableTiming) != cudaSuccess) return;
        ok = true;
    }
};
static StreamHolder g_sh;

// ---------------- launch ----------------
extern "C" void kernel_launch(void* const* d_in, const int* in_sizes, int n_in,
                              void* d_out, int out_size) {
    const float* x       = (const float*)d_in[0];
    const void*  eidx    = d_in[1];
    const void*  batch   = d_in[2];
    const float* W1      = (const float*)d_in[3];
    const float* asrc1   = (const float*)d_in[4];
    const float* adst1   = (const float*)d_in[5];
    const float* b1      = (const float*)d_in[6];
    const float* W2      = (const float*)d_in[7];
    const float* asrc2   = (const float*)d_in[8];
    const float* adst2   = (const float*)d_in[9];
    const float* b2      = (const float*)d_in[10];
    const float* Wf      = (const float*)d_in[11];
    const float* bf      = (const float*)d_in[12];
    float* out = (float*)d_out;

    const int TB = 256;
    const int cntGrid  = (N_EDGES / 2 + TB - 1) / TB;
    const int sctGrid  = (N_EDGES / 2 + N_NODES + TB - 1) / TB;
    const int nodeGrid = (N_NODES + TB - 1) / TB;
    const int aggGrid  = (N_NODES * 32 + TB - 1) / TB;

    if (g_sh.ok) {
        cudaEventRecord(g_sh.ev0, 0);
        cudaStreamWaitEvent(g_sh.s2, g_sh.ev0, 0);

        init_kernel<<<nodeGrid, TB, 0, g_sh.s2>>>(eidx);
        count_kernel<<<cntGrid, TB, 0, g_sh.s2>>>(eidx);
        scan1_kernel<<<N_SCAN_BLOCKS, SCAN_BS, 0, g_sh.s2>>>();
        scan2_kernel<<<1, 128, 0, g_sh.s2>>>();
        scan3_kernel<<<N_SCAN_BLOCKS, SCAN_BS, 0, g_sh.s2>>>();
        scatter_kernel<<<sctGrid, TB, 0, g_sh.s2>>>(eidx);
        cudaEventRecord(g_sh.ev1, g_sh.s2);

        gemm1_kernel<<<(N_NODES + G1_BN - 1) / G1_BN, 128>>>(x, W1, asrc1, adst1);

        cudaStreamWaitEvent(0, g_sh.ev1, 0);
    } else {
        init_kernel<<<nodeGrid, TB>>>(eidx);
        count_kernel<<<cntGrid, TB>>>(eidx);
        scan1_kernel<<<N_SCAN_BLOCKS, SCAN_BS>>>();
        scan2_kernel<<<1, 128>>>();
        scan3_kernel<<<N_SCAN_BLOCKS, SCAN_BS>>>();
        scatter_kernel<<<sctGrid, TB>>>(eidx);
        gemm1_kernel<<<(N_NODES + G1_BN - 1) / G1_BN, 128>>>(x, W1, asrc1, adst1);
    }

    agg1_kernel<<<aggGrid, TB>>>(b1, W2, asrc2, adst2);
    agg2_kernel<<<aggGrid, TB>>>(b2, batch);
    final_kernel<<<1, N_GRAPHS * OUT_DIM>>>(Wf, bf, out);
}

// round 16
// speedup vs baseline: 1.0658x; 1.0658x over previous
#include <cuda_runtime.h>
#include <cuda_bf16.h>

#define N_NODES   100000
#define N_EDGES   3200000
#define E_TOT     (N_EDGES + N_NODES)   // self loops appended
#define IN_DIM    512
#define HEADS     4
#define C1        8
#define C2        4
#define HC1       (HEADS*C1)   // 32
#define HC2       (HEADS*C2)   // 16
#define N_GRAPHS  64
#define OUT_DIM   10

#define SCAN_BS   1024
#define N_SCAN_BLOCKS ((N_NODES + SCAN_BS - 1) / SCAN_BS)   // 98

// ---------------- device scratch ----------------
// h1/h2 stored as packed bf16x2 (uint) rows: h1 row = 16 uints (64B), h2 row = 8 uints (32B)
__device__ __align__(16) unsigned g_h1b[(size_t)N_NODES * (HC1 / 2)];
__device__ __align__(16) float g_es1[(size_t)N_NODES * HEADS];
__device__ __align__(16) float g_ed1[(size_t)N_NODES * HEADS];

__device__ __align__(16) unsigned g_h2b[(size_t)N_NODES * (HC2 / 2)];
__device__ __align__(16) float g_es2[(size_t)N_NODES * HEADS];
__device__ __align__(16) float g_ed2[(size_t)N_NODES * HEADS];

__device__ __align__(16) float g_pool[N_GRAPHS * HC2];
__device__ float g_cnt [N_GRAPHS];

__device__ int g_deg[N_NODES];
__device__ int g_off[N_NODES + 1];
__device__ int g_pos[N_NODES];
__device__ int g_csr[E_TOT];
__device__ int g_blocksum[N_SCAN_BLOCKS];
__device__ int g_blockoff[N_SCAN_BLOCKS];

__device__ int g_is64;

// ---------------- helpers ----------------
__device__ __forceinline__ float lrelu(float v) { return v >= 0.f ? v : 0.2f * v; }

__device__ __forceinline__ void red4(float* p, float a, float b, float c, float d) {
    asm volatile("red.global.add.v4.f32 [%0], {%1,%2,%3,%4};"
                 :: "l"(p), "f"(a), "f"(b), "f"(c), "f"(d) : "memory");
}

__device__ __forceinline__ unsigned pack_bf2(float a, float b) {
    __nv_bfloat162 t = __floats2bfloat162_rn(a, b);
    return *(unsigned*)&t;
}
__device__ __forceinline__ float2 upk_bf2(unsigned u) {
    return __bfloat1622float2(*(__nv_bfloat162*)&u);
}

__device__ __forceinline__ void load_edge(const void* ei, int i, int is64, int& s, int& d) {
    if (i < N_EDGES) {
        if (is64) {
            const long long* p = (const long long*)ei;
            s = (int)p[i];
            d = (int)p[(size_t)N_EDGES + i];
        } else {
            const int* p = (const int*)ei;
            s = p[i];
            d = p[(size_t)N_EDGES + i];
        }
    } else {
        s = d = i - N_EDGES;
    }
}

// ---------------- init (fused dtype detect) ----------------
__global__ void init_kernel(const void* ei) {
    int t = blockIdx.x * blockDim.x + threadIdx.x;
    if (t < N_NODES) g_deg[t] = 0;
    if (t < N_GRAPHS * HC2) g_pool[t] = 0.f;
    if (t < N_GRAPHS)       g_cnt[t]  = 0.f;
    if (blockIdx.x == 0) {
        const unsigned long long* p = (const unsigned long long*)ei;
        int big = (p[threadIdx.x] >= (unsigned long long)N_NODES) ? 1 : 0;
        unsigned any_big = __ballot_sync(0xffffffffu, big);
        __shared__ unsigned sb[8];
        if ((threadIdx.x & 31) == 0) sb[threadIdx.x >> 5] = any_big;
        __syncthreads();
        if (threadIdx.x == 0) {
            unsigned m = 0;
            #pragma unroll
            for (int i = 0; i < 8; i++) m |= sb[i];
            g_is64 = (m == 0) ? 1 : 0;
        }
    }
}

// ---------------- CSR build ----------------
__global__ void count_kernel(const void* __restrict__ ei) {
    int i = blockIdx.x * blockDim.x + threadIdx.x;
    if (i >= E_TOT) return;
    int d;
    if (i < N_EDGES) {
        if (g_is64) d = (int)((const long long*)ei)[(size_t)N_EDGES + i];
        else        d = ((const int*)ei)[(size_t)N_EDGES + i];
    } else {
        d = i - N_EDGES;
    }
    atomicAdd(&g_deg[d], 1);
}

__global__ void scan1_kernel() {
    __shared__ int sm[SCAN_BS];
    const int t = threadIdx.x;
    const int idx = blockIdx.x * SCAN_BS + t;
    int v = (idx < N_NODES) ? g_deg[idx] : 0;
    sm[t] = v;
    __syncthreads();
    #pragma unroll
    for (int off = 1; off < SCAN_BS; off <<= 1) {
        int u = (t >= off) ? sm[t - off] : 0;
        __syncthreads();
        sm[t] += u;
        __syncthreads();
    }
    if (idx < N_NODES) g_off[idx] = sm[t] - v;
    if (t == SCAN_BS - 1) g_blocksum[blockIdx.x] = sm[t];
}

__global__ void scan2_kernel() {
    __shared__ int sm[128];
    const int t = threadIdx.x;
    int v = (t < N_SCAN_BLOCKS) ? g_blocksum[t] : 0;
    sm[t] = v;
    __syncthreads();
    #pragma unroll
    for (int off = 1; off < 128; off <<= 1) {
        int u = (t >= off) ? sm[t - off] : 0;
        __syncthreads();
        sm[t] += u;
        __syncthreads();
    }
    if (t < N_SCAN_BLOCKS) g_blockoff[t] = sm[t] - v;
}

__global__ void scan3_kernel() {
    const int idx = blockIdx.x * blockDim.x + threadIdx.x;
    if (idx < N_NODES) {
        int o = g_off[idx] + g_blockoff[blockIdx.x];
        g_off[idx] = o;
        g_pos[idx] = o;
    }
    if (idx == 0) g_off[N_NODES] = E_TOT;
}

__global__ void scatter_kernel(const void* __restrict__ ei) {
    int i = blockIdx.x * blockDim.x + threadIdx.x;
    if (i >= E_TOT) return;
    int s, d;
    load_edge(ei, i, g_is64, s, d);
    int p = atomicAdd(&g_pos[d], 1);
    g_csr[p] = s;
}

// ---------------- gemm1: h1 = x @ W1 (512->32), 8x8 register tile ------------
// scalar FMA (proven R6/R9); epilogue stores h1 as packed bf16x2 + fp32 scores.
#define G1_BN 256
#define G1_BK 32
__global__ __launch_bounds__(128) void gemm1_kernel(const float* __restrict__ x,
                                                    const float* __restrict__ W1,
                                                    const float* __restrict__ a_src,
                                                    const float* __restrict__ a_dst) {
    __shared__ float sX[G1_BN][36];
    __shared__ float sW[G1_BK][36];
    const int tid = threadIdx.x;
    const int nbase = blockIdx.x * G1_BN;
    const int ng = tid >> 2;
    const int cg = tid & 3;
    const int c0 = cg * 8;

    float4 acc[8][2];
    #pragma unroll
    for (int j = 0; j < 8; j++) { acc[j][0] = make_float4(0,0,0,0); acc[j][1] = make_float4(0,0,0,0); }

    for (int k0 = 0; k0 < IN_DIM; k0 += G1_BK) {
        __syncthreads();
        for (int i = tid; i < G1_BN * (G1_BK / 4); i += 128) {
            int n = i >> 3, kv = i & 7;
            float4 v = make_float4(0,0,0,0);
            if (nbase + n < N_NODES)
                v = *(const float4*)(x + (size_t)(nbase + n) * IN_DIM + k0 + kv * 4);
            *(float4*)&sX[n][kv * 4] = v;
        }
        for (int i = tid; i < G1_BK * 32; i += 128) {
            int k = i >> 5, c = i & 31;
            sW[k][c] = W1[(size_t)(k0 + k) * 32 + c];
        }
        __syncthreads();
        #pragma unroll
        for (int k4 = 0; k4 < G1_BK; k4 += 4) {
            float4 xt[8];
            #pragma unroll
            for (int j = 0; j < 8; j++) xt[j] = *(const float4*)&sX[ng + j * 32][k4];
            #pragma unroll
            for (int kk = 0; kk < 4; kk++) {
                float4 w0 = *(const float4*)&sW[k4 + kk][c0];
                float4 w1 = *(const float4*)&sW[k4 + kk][c0 + 4];
                #pragma unroll
                for (int j = 0; j < 8; j++) {
                    float xv = (kk == 0) ? xt[j].x : (kk == 1) ? xt[j].y : (kk == 2) ? xt[j].z : xt[j].w;
                    acc[j][0].x += xv * w0.x; acc[j][0].y += xv * w0.y;
                    acc[j][0].z += xv * w0.z; acc[j][0].w += xv * w0.w;
                    acc[j][1].x += xv * w1.x; acc[j][1].y += xv * w1.y;
                    acc[j][1].z += xv * w1.z; acc[j][1].w += xv * w1.w;
                }
            }
        }
    }

    float as0 = a_src[c0+0], as1 = a_src[c0+1], as2 = a_src[c0+2], as3 = a_src[c0+3];
    float as4 = a_src[c0+4], as5 = a_src[c0+5], as6 = a_src[c0+6], as7 = a_src[c0+7];
    float ad0 = a_dst[c0+0], ad1 = a_dst[c0+1], ad2 = a_dst[c0+2], ad3 = a_dst[c0+3];
    float ad4 = a_dst[c0+4], ad5 = a_dst[c0+5], ad6 = a_dst[c0+6], ad7 = a_dst[c0+7];
    #pragma unroll
    for (int j = 0; j < 8; j++) {
        int n = nbase + ng + j * 32;
        if (n >= N_NODES) continue;
        // packed bf16 store: 8 floats -> 4 uints (16B)
        uint4 hb;
        hb.x = pack_bf2(acc[j][0].x, acc[j][0].y);
        hb.y = pack_bf2(acc[j][0].z, acc[j][0].w);
        hb.z = pack_bf2(acc[j][1].x, acc[j][1].y);
        hb.w = pack_bf2(acc[j][1].z, acc[j][1].w);
        *(uint4*)&g_h1b[(size_t)n * (HC1/2) + cg * 4] = hb;
        float es = acc[j][0].x*as0 + acc[j][0].y*as1 + acc[j][0].z*as2 + acc[j][0].w*as3
                 + acc[j][1].x*as4 + acc[j][1].y*as5 + acc[j][1].z*as6 + acc[j][1].w*as7;
        float ed = acc[j][0].x*ad0 + acc[j][0].y*ad1 + acc[j][0].z*ad2 + acc[j][0].w*ad3
                 + acc[j][1].x*ad4 + acc[j][1].y*ad5 + acc[j][1].z*ad6 + acc[j][1].w*ad7;
        g_es1[(size_t)n * HEADS + cg] = es;
        g_ed1[(size_t)n * HEADS + cg] = ed;
    }
}

// ---------------- agg1: full-lane aggregation (bf16 gathers) + fused gemm2 ---
__global__ __launch_bounds__(256) void agg1_kernel(const float* __restrict__ b1,
                                                   const float* __restrict__ W2,
                                                   const float* __restrict__ a_src2,
                                                   const float* __restrict__ a_dst2) {
    __shared__ float sW2[HC1 * HC2];
    __shared__ __align__(16) float sB1[HC1];
    __shared__ float sA2s[HC2], sA2d[HC2];
    {
        const int t = threadIdx.x;
        for (int i = t; i < HC1 * HC2; i += 256) sW2[i] = W2[i];
        if (t < HC1) sB1[t] = b1[t];
        if (t < HC2) { sA2s[t] = a_src2[t]; sA2d[t] = a_dst2[t]; }
        __syncthreads();
    }

    const int warp = (blockIdx.x * blockDim.x + threadIdx.x) >> 5;
    if (warp >= N_NODES) return;
    const int lane = threadIdx.x & 31;
    const int d    = warp;
    const int beg  = g_off[d];
    const int end  = g_off[d + 1];
    const int le = lane >> 2, lh = lane & 3;   // exp phase: edge slot, head
    const int e  = lane >> 3, p = lane & 7;    // gather phase: edge-in-half, part
    const int hp = p >> 1;                     // head of part p

    const float edv_s = g_ed1[(size_t)d * 4 + lh];

    float  den_l = 0.f;
    float4 acc = make_float4(0,0,0,0);

    for (int base = beg; base < end; base += 8) {
        const int idx = base + le;
        int s_e = -1; float w = 0.f;
        if (idx < end) {
            s_e = g_csr[idx];
            float es_s = g_es1[(size_t)s_e * 4 + lh];
            w = __expf(lrelu(es_s + edv_s));
            den_l += w;
        }
        #pragma unroll
        for (int j = 0; j < 2; j++) {
            const int he = e + j * 4;                            // edge slot 0..7
            const int s_h = __shfl_sync(0xffffffffu, s_e, he * 4);
            const float w_h = __shfl_sync(0xffffffffu, w, he * 4 + hp);
            if (s_h >= 0) {
                uint2 hv = *(const uint2*)(g_h1b + (size_t)s_h * (HC1/2) + p * 2);
                float2 f0 = upk_bf2(hv.x), f1 = upk_bf2(hv.y);
                acc.x += w_h * f0.x; acc.y += w_h * f0.y;
                acc.z += w_h * f1.x; acc.w += w_h * f1.y;
            }
        }
    }

    // acc: reduce over lanes with same p (xor 8, 16)
    #pragma unroll
    for (int o = 8; o <= 16; o <<= 1) {
        acc.x += __shfl_xor_sync(0xffffffffu, acc.x, o);
        acc.y += __shfl_xor_sync(0xffffffffu, acc.y, o);
        acc.z += __shfl_xor_sync(0xffffffffu, acc.z, o);
        acc.w += __shfl_xor_sync(0xffffffffu, acc.w, o);
    }
    // den: reduce over edge slots (xor 4, 8, 16) -> every lane holds den[its lh]
    #pragma unroll
    for (int o = 4; o <= 16; o <<= 1)
        den_l += __shfl_xor_sync(0xffffffffu, den_l, o);
    const float den_h = __shfl_sync(0xffffffffu, den_l, hp);
    const float ih = 1.f / (den_h + 1e-16f);

    float4 bb = *(const float4*)&sB1[p * 4];
    float r0 = fmaxf(acc.x * ih + bb.x, 0.f);
    float r1 = fmaxf(acc.y * ih + bb.y, 0.f);
    float r2 = fmaxf(acc.z * ih + bb.z, 0.f);
    float r3 = fmaxf(acc.w * ih + bb.w, 0.f);

    // fused gemm2: lane computes partials for h2 cols e*4..e*4+3 over k = p*4..p*4+3
    const int k0 = p * 4, c0 = e * 4;
    float4 pc = make_float4(0,0,0,0);
    #pragma unroll
    for (int kk = 0; kk < 4; kk++) {
        float rv = kk == 0 ? r0 : kk == 1 ? r1 : kk == 2 ? r2 : r3;
        const float* wrow = &sW2[(k0 + kk) * HC2 + c0];
        pc.x += rv * wrow[0]; pc.y += rv * wrow[1];
        pc.z += rv * wrow[2]; pc.w += rv * wrow[3];
    }
    #pragma unroll
    for (int o = 1; o <= 4; o <<= 1) {
        pc.x += __shfl_xor_sync(0xffffffffu, pc.x, o);
        pc.y += __shfl_xor_sync(0xffffffffu, pc.y, o);
        pc.z += __shfl_xor_sync(0xffffffffu, pc.z, o);
        pc.w += __shfl_xor_sync(0xffffffffu, pc.w, o);
    }
    if (p == 0) {
        *(uint2*)&g_h2b[(size_t)d * (HC2/2) + e * 2] =
            make_uint2(pack_bf2(pc.x, pc.y), pack_bf2(pc.z, pc.w));
        float es = pc.x * sA2s[c0] + pc.y * sA2s[c0+1] + pc.z * sA2s[c0+2] + pc.w * sA2s[c0+3];
        float ed = pc.x * sA2d[c0] + pc.y * sA2d[c0+1] + pc.z * sA2d[c0+2] + pc.w * sA2d[c0+3];
        g_es2[(size_t)d * HEADS + e] = es;
        g_ed2[(size_t)d * HEADS + e] = ed;
    }
}

// ---------------- agg2: full-lane aggregation (bf16 gathers) + relu+pool -----
__global__ __launch_bounds__(256) void agg2_kernel(const float* __restrict__ b2,
                                                   const void* __restrict__ batch) {
    __shared__ __align__(16) float sB2[HC2];
    if (threadIdx.x < HC2) sB2[threadIdx.x] = b2[threadIdx.x];
    __syncthreads();

    const int warp = (blockIdx.x * blockDim.x + threadIdx.x) >> 5;
    if (warp >= N_NODES) return;
    const int lane = threadIdx.x & 31;
    const int d    = warp;
    const int beg  = g_off[d];
    const int end  = g_off[d + 1];
    const int le = lane >> 2, lh = lane & 3;

    const float edv_s = g_ed2[(size_t)d * 4 + lh];

    float  den_l = 0.f;
    float4 acc = make_float4(0,0,0,0);

    for (int base = beg; base < end; base += 8) {
        const int idx = base + le;
        if (idx < end) {
            int s = g_csr[idx];
            float es_s = g_es2[(size_t)s * 4 + lh];
            float w = __expf(lrelu(es_s + edv_s));
            den_l += w;
            uint2 hv = *(const uint2*)(g_h2b + (size_t)s * (HC2/2) + lh * 2);
            float2 f0 = upk_bf2(hv.x), f1 = upk_bf2(hv.y);
            acc.x += w * f0.x; acc.y += w * f0.y;
            acc.z += w * f1.x; acc.w += w * f1.y;
        }
    }

    #pragma unroll
    for (int o = 4; o <= 16; o <<= 1) {
        den_l += __shfl_xor_sync(0xffffffffu, den_l, o);
        acc.x += __shfl_xor_sync(0xffffffffu, acc.x, o);
        acc.y += __shfl_xor_sync(0xffffffffu, acc.y, o);
        acc.z += __shfl_xor_sync(0xffffffffu, acc.z, o);
        acc.w += __shfl_xor_sync(0xffffffffu, acc.w, o);
    }

    if (lane < 4) {
        int g;
        if (g_is64) g = (int)((const long long*)batch)[d];
        else        g = ((const int*)batch)[d];
        const float ih = 1.f / (den_l + 1e-16f);
        float4 bb = *(const float4*)&sB2[lane * 4];
        float o0 = fmaxf(acc.x * ih + bb.x, 0.f);
        float o1 = fmaxf(acc.y * ih + bb.y, 0.f);
        float o2 = fmaxf(acc.z * ih + bb.z, 0.f);
        float o3 = fmaxf(acc.w * ih + bb.w, 0.f);
        red4(g_pool + g * HC2 + lane * 4, o0, o1, o2, o3);
        if (lane == 0) atomicAdd(&g_cnt[g], 1.f);
    }
}

// ---------------- final ----------------
__global__ void final_kernel(const float* __restrict__ Wf, const float* __restrict__ bf,
                             float* __restrict__ out) {
    const int t = threadIdx.x;
    if (t >= N_GRAPHS * OUT_DIM) return;
    const int g = t / OUT_DIM;
    const int o = t % OUT_DIM;
    const float c = fmaxf(g_cnt[g], 1.f);
    float acc = bf[o];
    #pragma unroll
    for (int j = 0; j < HC2; j++)
        acc += (g_pool[g * HC2 + j] / c) * Wf[j * OUT_DIM + o];
    out[t] = acc;
}

// ---------------- stream/event holder ----------------
struct StreamHolder {
    cudaStream_t s2 = nullptr;
    cudaEvent_t  ev0 = nullptr, ev1 = nullptr;
    bool ok = false;
    StreamHolder() {
        if (cudaStreamCreateWithFlags(&s2, cudaStreamNonBlocking) != cudaSuccess) return;
        if (cudaEventCreateWithFlags(&ev0, cudaEventDisableTiming) != cudaSuccess) return;
        if (cudaEventCreateWithFlags(&ev1, cudaEventDisableTiming) != cudaSuccess) return;
        ok = true;
    }
};
static StreamHolder g_sh;

// ---------------- launch ----------------
extern "C" void kernel_launch(void* const* d_in, const int* in_sizes, int n_in,
                              void* d_out, int out_size) {
    const float* x       = (const float*)d_in[0];
    const void*  eidx    = d_in[1];
    const void*  batch   = d_in[2];
    const float* W1      = (const float*)d_in[3];
    const float* asrc1   = (const float*)d_in[4];
    const float* adst1   = (const float*)d_in[5];
    const float* b1      = (const float*)d_in[6];
    const float* W2      = (const float*)d_in[7];
    const float* asrc2   = (const float*)d_in[8];
    const float* adst2   = (const float*)d_in[9];
    const float* b2      = (const float*)d_in[10];
    const float* Wf      = (const float*)d_in[11];
    const float* bf      = (const float*)d_in[12];
    float* out = (float*)d_out;

    const int TB = 256;
    const int edgeGrid = (E_TOT + TB - 1) / TB;
    const int nodeGrid = (N_NODES + TB - 1) / TB;
    const int aggGrid  = (N_NODES * 32 + TB - 1) / TB;

    if (g_sh.ok) {
        cudaEventRecord(g_sh.ev0, 0);
        cudaStreamWaitEvent(g_sh.s2, g_sh.ev0, 0);

        init_kernel<<<nodeGrid, TB, 0, g_sh.s2>>>(eidx);
        count_kernel<<<edgeGrid, TB, 0, g_sh.s2>>>(eidx);
        scan1_kernel<<<N_SCAN_BLOCKS, SCAN_BS, 0, g_sh.s2>>>();
        scan2_kernel<<<1, 128, 0, g_sh.s2>>>();
        scan3_kernel<<<N_SCAN_BLOCKS, SCAN_BS, 0, g_sh.s2>>>();
        scatter_kernel<<<edgeGrid, TB, 0, g_sh.s2>>>(eidx);
        cudaEventRecord(g_sh.ev1, g_sh.s2);

        gemm1_kernel<<<(N_NODES + G1_BN - 1) / G1_BN, 128>>>(x, W1, asrc1, adst1);

        cudaStreamWaitEvent(0, g_sh.ev1, 0);
    } else {
        init_kernel<<<nodeGrid, TB>>>(eidx);
        count_kernel<<<edgeGrid, TB>>>(eidx);
        scan1_kernel<<<N_SCAN_BLOCKS, SCAN_BS>>>();
        scan2_kernel<<<1, 128>>>();
        scan3_kernel<<<N_SCAN_BLOCKS, SCAN_BS>>>();
        scatter_kernel<<<edgeGrid, TB>>>(eidx);
        gemm1_kernel<<<(N_NODES + G1_BN - 1) / G1_BN, 128>>>(x, W1, asrc1, adst1);
    }

    agg1_kernel<<<aggGrid, TB>>>(b1, W2, asrc2, adst2);
    agg2_kernel<<<aggGrid, TB>>>(b2, batch);
    final_kernel<<<1, N_GRAPHS * OUT_DIM>>>(Wf, bf, out);
}